// round 2
// baseline (speedup 1.0000x reference)
#include <cuda_runtime.h>
#include <math.h>

#define BB   8
#define NTOK 1024
#define CC   768
#define NSTR 6
#define BN   (BB*NTOK)          // 8192
#define ROWS (NSTR*BN)          // 49152
#define HID  3072
#define POUT 1536

// ---------------- scratch (device globals: no runtime allocation allowed) ---
__device__ float  g_ln [(size_t)ROWS*CC];   // LN1 outputs, later reused for LN2
__device__ float  g_qk [(size_t)ROWS*CC];
__device__ float  g_v  [(size_t)ROWS*CC];
__device__ float  g_x2 [ROWS];
__device__ float  g_Dm [(size_t)BB*NTOK*NTOK];
__device__ double g_rs1[BN], g_rs2[BN], g_cs1[BN], g_cs2[BN];
__device__ float  g_invr[BN], g_invc[BN];
__device__ unsigned int g_minu, g_maxu;
__device__ float  g_map[ROWS];
__device__ float  g_hid[(size_t)ROWS*HID];

// ---------------- block reduce helpers -------------------------------------
__device__ __forceinline__ float blk_sum(float v){
    __shared__ float sh[32];
    int t = threadIdx.x;
    __syncthreads();
    #pragma unroll
    for (int o=16;o;o>>=1) v += __shfl_down_sync(~0u, v, o);
    if ((t&31)==0) sh[t>>5]=v;
    __syncthreads();
    if (t<32){
        float r = (t < ((int)blockDim.x+31)/32) ? sh[t] : 0.f;
        #pragma unroll
        for (int o=16;o;o>>=1) r += __shfl_down_sync(~0u, r, o);
        if (t==0) sh[0]=r;
    }
    __syncthreads();
    return sh[0];
}
__device__ __forceinline__ double blk_sum_d(double v){
    __shared__ double sh[32];
    int t = threadIdx.x;
    __syncthreads();
    #pragma unroll
    for (int o=16;o;o>>=1) v += __shfl_down_sync(~0u, v, o);
    if ((t&31)==0) sh[t>>5]=v;
    __syncthreads();
    if (t<32){
        double r = (t < ((int)blockDim.x+31)/32) ? sh[t] : 0.0;
        #pragma unroll
        for (int o=16;o;o>>=1) r += __shfl_down_sync(~0u, r, o);
        if (t==0) sh[0]=r;
    }
    __syncthreads();
    return sh[0];
}
__device__ __forceinline__ float blk_min(float v){
    __shared__ float sh[32];
    int t = threadIdx.x;
    __syncthreads();
    #pragma unroll
    for (int o=16;o;o>>=1) v = fminf(v, __shfl_down_sync(~0u, v, o));
    if ((t&31)==0) sh[t>>5]=v;
    __syncthreads();
    if (t<32){
        float r = (t < ((int)blockDim.x+31)/32) ? sh[t] : 3.4e38f;
        #pragma unroll
        for (int o=16;o;o>>=1) r = fminf(r, __shfl_down_sync(~0u, r, o));
        if (t==0) sh[0]=r;
    }
    __syncthreads();
    return sh[0];
}
__device__ __forceinline__ float blk_max(float v){
    __shared__ float sh[32];
    int t = threadIdx.x;
    __syncthreads();
    #pragma unroll
    for (int o=16;o;o>>=1) v = fmaxf(v, __shfl_down_sync(~0u, v, o));
    if ((t&31)==0) sh[t>>5]=v;
    __syncthreads();
    if (t<32){
        float r = (t < ((int)blockDim.x+31)/32) ? sh[t] : -3.4e38f;
        #pragma unroll
        for (int o=16;o;o>>=1) r = fmaxf(r, __shfl_down_sync(~0u, r, o));
        if (t==0) sh[0]=r;
    }
    __syncthreads();
    return sh[0];
}

// ---------------- layernorm kernels -----------------------------------------
__global__ __launch_bounds__(256)
void k_ln_gather(const float* __restrict__ anc, const float* __restrict__ pos,
                 const float* __restrict__ n1,  const float* __restrict__ n2,
                 const float* __restrict__ w,   const float* __restrict__ b)
{
    __shared__ float xs[CC];
    int r = blockIdx.x;
    int s = r / BN, i = r % BN;
    const float* src;
    if (s==0)       src = anc + (size_t)i*CC;
    else if (s==1)  src = pos + (size_t)i*CC;
    else if (s<4)   src = n1 + ((size_t)(s-2)*BN + i)*CC;
    else            src = n2 + ((size_t)(s-4)*BN + i)*CC;
    int t = threadIdx.x;
    float ls = 0.f;
    for (int c=t;c<CC;c+=256){ float v=src[c]; xs[c]=v; ls+=v; }
    float mu = blk_sum(ls) * (1.f/CC);
    float lv = 0.f;
    for (int c=t;c<CC;c+=256){ float d=xs[c]-mu; lv += d*d; }
    float var = blk_sum(lv) * (1.f/CC);
    float inv = rsqrtf(var + 1e-5f);
    float* dst = g_ln + (size_t)r*CC;
    for (int c=t;c<CC;c+=256) dst[c] = (xs[c]-mu)*inv*w[c] + b[c];
}

__global__ __launch_bounds__(256)
void k_ln_plain(const float* __restrict__ in, const float* __restrict__ w,
                const float* __restrict__ b)
{
    __shared__ float xs[CC];
    int r = blockIdx.x;
    const float* src = in + (size_t)r*CC;
    int t = threadIdx.x;
    float ls = 0.f;
    for (int c=t;c<CC;c+=256){ float v=src[c]; xs[c]=v; ls+=v; }
    float mu = blk_sum(ls) * (1.f/CC);
    float lv = 0.f;
    for (int c=t;c<CC;c+=256){ float d=xs[c]-mu; lv += d*d; }
    float var = blk_sum(lv) * (1.f/CC);
    float inv = rsqrtf(var + 1e-5f);
    float* dst = g_ln + (size_t)r*CC;
    for (int c=t;c<CC;c+=256) dst[c] = (xs[c]-mu)*inv*w[c] + b[c];
}

// ---------------- misc small kernels ----------------------------------------
__global__ __launch_bounds__(256)
void k_x2(){
    int r = blockIdx.x;
    const float* row = g_qk + (size_t)r*CC;
    float s = 0.f;
    for (int c=threadIdx.x;c<CC;c+=256){ float v=row[c]; s += v*v; }
    s = blk_sum(s);
    if (threadIdx.x==0) g_x2[r] = s;
}

__global__ __launch_bounds__(256)
void k_zero_map(){
    int i = blockIdx.x*256 + threadIdx.x;
    if (i < ROWS) g_map[i] = 0.f;
}

__global__ __launch_bounds__(256)
void k_reset(){
    int i = blockIdx.x*256 + threadIdx.x;
    if (i < BN){ g_cs1[i]=0.0; g_cs2[i]=0.0; }
    if (i==0){ g_minu = 0x7f7fffffu; g_maxu = 0u; }
}

// ---------------- GEMM ------------------------------------------------------
#define EPI_PROJ 1
#define EPI_DIST 2
#define EPI_FC1  3
#define EPI_FC2  4

template<bool BT, int EPI>
__global__ __launch_bounds__(256)
void gemm_k(const float* __restrict__ A, const float* __restrict__ Bm,
            float* __restrict__ Co, float* __restrict__ Co2,
            const float* __restrict__ bias,
            const float* __restrict__ x2a, const float* __restrict__ x2b,
            int M, int Nn, int K,
            long strideA, long strideB, long strideC)
{
    __shared__ float As[16][128];
    __shared__ float Bs[16][128];
    const int bz = blockIdx.z;
    const float* Ab = A + (size_t)bz*strideA;
    const float* Bb = Bm + (size_t)bz*strideB;
    const int m0 = blockIdx.y * 128;
    const int n0 = blockIdx.x * 128;
    const int tid = threadIdx.x;
    const int tx = tid & 15, ty = tid >> 4;

    float acc[8][8];
    #pragma unroll
    for (int i=0;i<8;i++)
        #pragma unroll
        for (int j=0;j<8;j++) acc[i][j]=0.f;

    for (int k0=0; k0<K; k0+=16) {
        #pragma unroll
        for (int l=0;l<2;l++){
            int f   = tid + l*256;
            int row = f >> 2;
            int c4  = (f & 3) << 2;
            float4 v = *(const float4*)(Ab + (size_t)(m0+row)*K + k0 + c4);
            As[c4+0][row]=v.x; As[c4+1][row]=v.y; As[c4+2][row]=v.z; As[c4+3][row]=v.w;
        }
        if (BT) {
            #pragma unroll
            for (int l=0;l<2;l++){
                int f   = tid + l*256;
                int row = f >> 2;
                int c4  = (f & 3) << 2;
                float4 v = *(const float4*)(Bb + (size_t)(n0+row)*K + k0 + c4);
                Bs[c4+0][row]=v.x; Bs[c4+1][row]=v.y; Bs[c4+2][row]=v.z; Bs[c4+3][row]=v.w;
            }
        } else {
            #pragma unroll
            for (int l=0;l<2;l++){
                int f  = tid + l*256;
                int kr = f >> 5;
                int c4 = (f & 31) << 2;
                float4 v = *(const float4*)(Bb + (size_t)(k0+kr)*Nn + n0 + c4);
                *(float4*)&Bs[kr][c4] = v;
            }
        }
        __syncthreads();
        #pragma unroll
        for (int kk=0;kk<16;kk++){
            float a[8], bq[8];
            *(float4*)&a[0]  = *(const float4*)&As[kk][ty*8];
            *(float4*)&a[4]  = *(const float4*)&As[kk][ty*8+4];
            *(float4*)&bq[0] = *(const float4*)&Bs[kk][tx*8];
            *(float4*)&bq[4] = *(const float4*)&Bs[kk][tx*8+4];
            #pragma unroll
            for (int i=0;i<8;i++)
                #pragma unroll
                for (int j=0;j<8;j++)
                    acc[i][j] = fmaf(a[i], bq[j], acc[i][j]);
        }
        __syncthreads();
    }

    float* Cb = Co + (size_t)bz*strideC;
    #pragma unroll
    for (int i=0;i<8;i++){
        int m = m0 + ty*8 + i;
        #pragma unroll
        for (int j=0;j<8;j++){
            int n = n0 + tx*8 + j;
            float v = acc[i][j];
            if (EPI==EPI_PROJ){
                v += bias[n];
                if (n < CC) Cb [(size_t)m*CC + n]        = v;
                else        Co2[(size_t)m*CC + (n-CC)]   = v;
            } else if (EPI==EPI_DIST){
                float d2 = x2a[bz*NTOK+m] + x2b[bz*NTOK+n] - 2.0f*v;
                Cb[(size_t)m*NTOK + n] = sqrtf(fmaxf(d2, 1e-12f));
            } else if (EPI==EPI_FC1){
                v += bias[n];
                v = 0.5f*v*(1.0f + erff(v*0.70710678118654752f));
                Cb[(size_t)m*Nn + n] = v;
            } else if (EPI==EPI_FC2){
                v += bias[n];
                Cb[(size_t)m*Nn + n] += v;
            }
        }
    }
}

// ---------------- distance-matrix reductions --------------------------------
__global__ __launch_bounds__(256)
void k_rowstats(){
    int r = blockIdx.x; int b = r>>10, i = r&1023;
    const float* row = g_Dm + ((size_t)b<<20) + ((size_t)i<<10);
    double s1=0.0, s2=0.0; float mn=3.4e38f, mx=0.f;
    for (int j=threadIdx.x;j<NTOK;j+=256){
        float v = row[j];
        s1 += v; s2 += (double)v*(double)v;
        mn = fminf(mn,v); mx = fmaxf(mx,v);
    }
    s1 = blk_sum_d(s1); s2 = blk_sum_d(s2);
    mn = blk_min(mn);   mx = blk_max(mx);
    if (threadIdx.x==0){
        g_rs1[r]=s1; g_rs2[r]=s2;
        atomicMin(&g_minu, __float_as_uint(mn));
        atomicMax(&g_maxu, __float_as_uint(mx));
    }
}

__global__ __launch_bounds__(256)
void k_colstats(){
    int b = blockIdx.y;
    int j = blockIdx.x*256 + threadIdx.x;
    int i0 = blockIdx.z*128;
    const float* base = g_Dm + ((size_t)b<<20) + j;
    double s1a=0.0,s1b=0.0,s2a=0.0,s2b=0.0;
    #pragma unroll 4
    for (int i=i0;i<i0+128;i+=2){
        float v0 = base[(size_t)i<<10];
        float v1 = base[(size_t)(i+1)<<10];
        s1a += v0; s2a += (double)v0*(double)v0;
        s1b += v1; s2b += (double)v1*(double)v1;
    }
    atomicAdd(&g_cs1[b*NTOK+j], s1a+s1b);
    atomicAdd(&g_cs2[b*NTOK+j], s2a+s2b);
}

__global__ __launch_bounds__(256)
void k_finalize(int useMax){
    int idx = blockIdx.x*256 + threadIdx.x;
    double t = (double)(useMax ? __uint_as_float(g_maxu) : __uint_as_float(g_minu));
    if (idx < BN){
        double ss = g_rs2[idx] - 2.0*t*g_rs1[idx] + (double)NTOK*t*t;
        float nrm = (float)sqrt(fmax(ss, 0.0));
        g_invr[idx] = 1.0f / fmaxf(nrm, 1e-12f);
    } else if (idx < 2*BN){
        int j = idx - BN;
        double ss = g_cs2[j] - 2.0*t*g_cs1[j] + (double)NTOK*t*t;
        float nrm = (float)sqrt(fmax(ss, 0.0));
        g_invc[j] = 1.0f / fmaxf(nrm, 1e-12f);
    }
}

__device__ __forceinline__ void get_tsc(const float* theta, const float* alpha,
                                        int wsel, float& t, float& sc){
    if (wsel==0){ t = __uint_as_float(g_maxu); sc = -1.f; }
    else {
        float kk = tanhf(*theta) + 1.f;
        float al = 1.f/(1.f + expf(-*alpha));
        t = __uint_as_float(g_minu);
        sc = 0.5f*kk*((wsel==1)? al : (1.f-al));
    }
}

// out[b,j] += sc * sum_i (D_ij - t) * invr[b,i]   (i-chunked via blockIdx.z)
__global__ __launch_bounds__(256)
void k_accum_col(float* __restrict__ outMap, const float* __restrict__ theta,
                 const float* __restrict__ alpha, int wsel)
{
    int b = blockIdx.y;
    int j = blockIdx.x*256 + threadIdx.x;
    int i0 = blockIdx.z*128;
    float t, sc; get_tsc(theta, alpha, wsel, t, sc);
    const float* base = g_Dm + ((size_t)b<<20) + j;
    const float* ir = g_invr + b*NTOK;
    float s=0.f;
    #pragma unroll 4
    for (int i=i0;i<i0+128;i++)
        s += (base[(size_t)i<<10] - t) * ir[i];
    atomicAdd(&outMap[b*NTOK + j], sc*s);
}

// out[b,i] += sc * sum_j (D_ij - t) * invc[b,j]
__global__ __launch_bounds__(256)
void k_accum_row(float* __restrict__ outMap, const float* __restrict__ theta,
                 const float* __restrict__ alpha, int wsel)
{
    int r = blockIdx.x; int b = r>>10, i = r&1023;
    float t, sc; get_tsc(theta, alpha, wsel, t, sc);
    const float* row = g_Dm + ((size_t)b<<20) + ((size_t)i<<10);
    const float* ic = g_invc + b*NTOK;
    float s=0.f;
    for (int j=threadIdx.x;j<NTOK;j+=256)
        s += (row[j]-t) * ic[j];
    s = blk_sum(s);
    if (threadIdx.x==0) outMap[r] += sc*s;
}

// ---------------- stage D ---------------------------------------------------
__global__ __launch_bounds__(256)
void k_stage_d(float* __restrict__ out){
    int r = blockIdx.x; int s = r / BN;
    float mp = g_map[r];
    size_t off = (size_t)r*CC;
    for (int c=threadIdx.x;c<CC;c+=256){
        float vv = g_v[off+c], ll = g_ln[off+c];
        out[off+c] = (s<2) ? fmaf(mp, vv, ll) : mp*vv*ll;
    }
}

// ---------------- host orchestration ----------------------------------------
static int wsel_for(int neg, int tgt){
    int gn = neg>>1, gt = tgt>>1;
    int algroup = (gt==0) ? 1 : 0;
    return (gn==algroup) ? 1 : 2;
}

extern "C" void kernel_launch(void* const* d_in, const int* in_sizes, int n_in,
                              void* d_out, int out_size)
{
    const float* anchor   = (const float*)d_in[0];
    const float* positive = (const float*)d_in[1];
    const float* neg1     = (const float*)d_in[2];
    const float* neg2     = (const float*)d_in[3];
    const float* n1w      = (const float*)d_in[4];
    const float* n1b      = (const float*)d_in[5];
    const float* n2w      = (const float*)d_in[6];
    const float* n2b      = (const float*)d_in[7];
    const float* projW    = (const float*)d_in[8];
    const float* projB    = (const float*)d_in[9];
    const float* fc1W     = (const float*)d_in[10];
    const float* fc1B     = (const float*)d_in[11];
    const float* fc2W     = (const float*)d_in[12];
    const float* fc2B     = (const float*)d_in[13];
    const float* theta    = (const float*)d_in[14];
    const float* alpha    = (const float*)d_in[15];
    float* out = (float*)d_out;

    float *p_ln, *p_qk, *p_v, *p_x2, *p_map, *p_hid, *p_Dm;
    cudaGetSymbolAddress((void**)&p_ln,  g_ln);
    cudaGetSymbolAddress((void**)&p_qk,  g_qk);
    cudaGetSymbolAddress((void**)&p_v,   g_v);
    cudaGetSymbolAddress((void**)&p_x2,  g_x2);
    cudaGetSymbolAddress((void**)&p_map, g_map);
    cudaGetSymbolAddress((void**)&p_hid, g_hid);
    cudaGetSymbolAddress((void**)&p_Dm,  g_Dm);

    k_zero_map<<<ROWS/256, 256>>>();
    k_ln_gather<<<ROWS, 256>>>(anchor, positive, neg1, neg2, n1w, n1b);

    // projection: (49152 x 768) @ (768 x 1536) -> split qk | v
    gemm_k<false, EPI_PROJ><<<dim3(POUT/128, ROWS/128, 1), 256>>>(
        p_ln, projW, p_qk, p_v, projB, nullptr, nullptr,
        ROWS, POUT, CC, 0, 0, 0);

    k_x2<<<ROWS, 256>>>();

    // 3 within-group "S_p" pairs (max-shift) + 12 cross-group "proc" pairs (min-shift)
    const int PU[15] = {1,3,5, 0,0,0,0, 1,1,1,1, 2,2,3,3};
    const int PW[15] = {0,2,4, 2,3,4,5, 2,3,4,5, 4,5,4,5};
    for (int p=0;p<15;p++){
        int u = PU[p], w = PW[p];
        bool sp = (p<3);
        k_reset<<<BN/256, 256>>>();
        gemm_k<true, EPI_DIST><<<dim3(NTOK/128, NTOK/128, BB), 256>>>(
            p_qk + (size_t)u*BN*CC, p_qk + (size_t)w*BN*CC,
            p_Dm, nullptr, nullptr,
            p_x2 + u*BN, p_x2 + w*BN,
            NTOK, NTOK, CC,
            (long)NTOK*CC, (long)NTOK*CC, (long)NTOK*NTOK);
        k_rowstats<<<BN, 256>>>();
        k_colstats<<<dim3(NTOK/256, BB, 8), 256>>>();
        k_finalize<<<(2*BN)/256, 256>>>(sp ? 1 : 0);
        k_accum_col<<<dim3(NTOK/256, BB, 8), 256>>>(
            p_map + (size_t)w*BN, theta, alpha, sp ? 0 : wsel_for(u,w));
        k_accum_row<<<BN, 256>>>(
            p_map + (size_t)u*BN, theta, alpha, sp ? 0 : wsel_for(w,u));
    }

    k_stage_d<<<ROWS, 256>>>(out);
    k_ln_plain<<<ROWS, 256>>>(out, n2w, n2b);

    gemm_k<false, EPI_FC1><<<dim3(HID/128, ROWS/128, 1), 256>>>(
        p_ln, fc1W, p_hid, nullptr, fc1B, nullptr, nullptr,
        ROWS, HID, CC, 0, 0, 0);
    gemm_k<false, EPI_FC2><<<dim3(CC/128, ROWS/128, 1), 256>>>(
        p_hid, fc2W, out, nullptr, fc2B, nullptr, nullptr,
        ROWS, CC, HID, 0, 0, 0);
}

// round 3
// speedup vs baseline: 5.1883x; 5.1883x over previous
#include <cuda_runtime.h>
#include <math.h>

#define BB    8
#define NTOK  1024
#define CC    768
#define BN    (BB*NTOK)          // 8192
#define ROWS  (6*BN)             // 49152
#define HID   3072
#define POUT  1536
#define NPAIR 15
#define ZTOT  (NPAIR*BB)         // 120

// ---------------- scratch ----------------------------------------------------
__device__ float g_ln [(size_t)ROWS*CC];
__device__ float g_qk [(size_t)ROWS*CC];
__device__ float g_v  [(size_t)ROWS*CC];
__device__ float g_x2 [ROWS];
__device__ float g_Dm [(size_t)ZTOT*NTOK*NTOK];      // 503 MB
__device__ float g_rc [ZTOT*NTOK], g_rs1[ZTOT*NTOK], g_rs2[ZTOT*NTOK];
__device__ float g_cc [ZTOT*NTOK], g_cs1[ZTOT*NTOK], g_cs2[ZTOT*NTOK];
__device__ float g_invr[ZTOT*NTOK], g_invc[ZTOT*NTOK];
__device__ unsigned g_minu[NPAIR], g_maxu[NPAIR];
__device__ float g_map[ROWS];
__device__ float g_hid[(size_t)ROWS*HID];

// pair tables (computed to match the verified R2 per-pair logic)
__constant__ int c_PU[NPAIR] = {1,3,5, 0,0,0,0, 1,1,1,1, 2,2,3,3};
__constant__ int c_PW[NPAIR] = {0,2,4, 2,3,4,5, 2,3,4,5, 4,5,4,5};
__constant__ int c_WC[NPAIR] = {0,0,0, 1,1,1,1, 1,1,1,1, 2,2,2,2};
__constant__ int c_WR[NPAIR] = {0,0,0, 1,1,2,2, 1,1,2,2, 2,2,2,2};

// ---------------- helpers ----------------------------------------------------
__device__ __forceinline__ float wsum(float v){
    #pragma unroll
    for (int o=16;o;o>>=1) v += __shfl_xor_sync(~0u, v, o);
    return v;
}
__device__ __forceinline__ float wmin(float v){
    #pragma unroll
    for (int o=16;o;o>>=1) v = fminf(v, __shfl_xor_sync(~0u, v, o));
    return v;
}
__device__ __forceinline__ float wmax(float v){
    #pragma unroll
    for (int o=16;o;o>>=1) v = fmaxf(v, __shfl_xor_sync(~0u, v, o));
    return v;
}
__device__ __forceinline__ unsigned f2tf(float x){
    unsigned r; asm("cvt.rna.tf32.f32 %0, %1;" : "=r"(r) : "f"(x)); return r;
}
__device__ __forceinline__ void mma8(float* c, const unsigned* a, const unsigned* b){
    asm volatile("mma.sync.aligned.m16n8k8.row.col.f32.tf32.tf32.f32 "
        "{%0,%1,%2,%3}, {%4,%5,%6,%7}, {%8,%9}, {%0,%1,%2,%3};"
        : "+f"(c[0]),"+f"(c[1]),"+f"(c[2]),"+f"(c[3])
        : "r"(a[0]),"r"(a[1]),"r"(a[2]),"r"(a[3]), "r"(b[0]),"r"(b[1]));
}
__device__ __forceinline__ float calc_sc(int wsel, float th, float al){
    if (wsel==0) return -1.f;
    float kk = tanhf(th) + 1.f;
    float a  = 1.f/(1.f + expf(-al));
    return 0.5f*kk*((wsel==1)? a : (1.f-a));
}

// ---------------- layernorm / elementwise ------------------------------------
__global__ __launch_bounds__(256)
void k_ln_gather(const float* __restrict__ anc, const float* __restrict__ pos,
                 const float* __restrict__ n1,  const float* __restrict__ n2,
                 const float* __restrict__ w,   const float* __restrict__ b)
{
    int r = blockIdx.x*8 + (threadIdx.x>>5);
    int lane = threadIdx.x & 31;
    int s = r / BN, i = r % BN;
    const float* src;
    if (s==0)       src = anc + (size_t)i*CC;
    else if (s==1)  src = pos + (size_t)i*CC;
    else if (s<4)   src = n1 + ((size_t)(s-2)*BN + i)*CC;
    else            src = n2 + ((size_t)(s-4)*BN + i)*CC;
    const float4* p4 = (const float4*)src;
    float4 v[6]; float ls = 0.f;
    #pragma unroll
    for (int q=0;q<6;q++){ v[q] = p4[lane+32*q]; ls += v[q].x+v[q].y+v[q].z+v[q].w; }
    float mu = wsum(ls) * (1.f/CC);
    float lv = 0.f;
    #pragma unroll
    for (int q=0;q<6;q++){
        float a0=v[q].x-mu, a1=v[q].y-mu, a2=v[q].z-mu, a3=v[q].w-mu;
        lv += a0*a0 + a1*a1 + a2*a2 + a3*a3;
    }
    float inv = rsqrtf(wsum(lv)*(1.f/CC) + 1e-5f);
    float4* dst = (float4*)(g_ln + (size_t)r*CC);
    const float4* w4 = (const float4*)w; const float4* b4 = (const float4*)b;
    #pragma unroll
    for (int q=0;q<6;q++){
        int idx = lane + 32*q;
        float4 ww = w4[idx], bb = b4[idx], o;
        o.x = (v[q].x-mu)*inv*ww.x + bb.x;
        o.y = (v[q].y-mu)*inv*ww.y + bb.y;
        o.z = (v[q].z-mu)*inv*ww.z + bb.z;
        o.w = (v[q].w-mu)*inv*ww.w + bb.w;
        dst[idx] = o;
    }
}

__global__ __launch_bounds__(256)
void k_ln_plain(const float* __restrict__ in, const float* __restrict__ w,
                const float* __restrict__ b)
{
    int r = blockIdx.x*8 + (threadIdx.x>>5);
    int lane = threadIdx.x & 31;
    const float4* p4 = (const float4*)(in + (size_t)r*CC);
    float4 v[6]; float ls = 0.f;
    #pragma unroll
    for (int q=0;q<6;q++){ v[q] = p4[lane+32*q]; ls += v[q].x+v[q].y+v[q].z+v[q].w; }
    float mu = wsum(ls) * (1.f/CC);
    float lv = 0.f;
    #pragma unroll
    for (int q=0;q<6;q++){
        float a0=v[q].x-mu, a1=v[q].y-mu, a2=v[q].z-mu, a3=v[q].w-mu;
        lv += a0*a0 + a1*a1 + a2*a2 + a3*a3;
    }
    float inv = rsqrtf(wsum(lv)*(1.f/CC) + 1e-5f);
    float4* dst = (float4*)(g_ln + (size_t)r*CC);
    const float4* w4 = (const float4*)w; const float4* b4 = (const float4*)b;
    #pragma unroll
    for (int q=0;q<6;q++){
        int idx = lane + 32*q;
        float4 ww = w4[idx], bb = b4[idx], o;
        o.x = (v[q].x-mu)*inv*ww.x + bb.x;
        o.y = (v[q].y-mu)*inv*ww.y + bb.y;
        o.z = (v[q].z-mu)*inv*ww.z + bb.z;
        o.w = (v[q].w-mu)*inv*ww.w + bb.w;
        dst[idx] = o;
    }
}

__global__ __launch_bounds__(256)
void k_x2(){
    int r = blockIdx.x*8 + (threadIdx.x>>5);
    int lane = threadIdx.x & 31;
    const float4* p4 = (const float4*)(g_qk + (size_t)r*CC);
    float s = 0.f;
    #pragma unroll
    for (int q=0;q<6;q++){
        float4 v = p4[lane+32*q];
        s += v.x*v.x + v.y*v.y + v.z*v.z + v.w*v.w;
    }
    s = wsum(s);
    if (lane==0) g_x2[r] = s;
}

__global__ __launch_bounds__(256)
void k_zero_map(){
    int i = blockIdx.x*256 + threadIdx.x;
    if (i < ROWS) g_map[i] = 0.f;
}

__global__ void k_reset(){
    int i = threadIdx.x;
    if (i < NPAIR){ g_minu[i] = 0x7f7fffffu; g_maxu[i] = 0u; }
}

__global__ __launch_bounds__(256)
void k_stage_d(float* __restrict__ out){
    int r = blockIdx.x*8 + (threadIdx.x>>5);
    int lane = threadIdx.x & 31;
    int s = r / BN;
    float mp = g_map[r];
    const float4* v4 = (const float4*)(g_v  + (size_t)r*CC);
    const float4* l4 = (const float4*)(g_ln + (size_t)r*CC);
    float4* o4 = (float4*)(out + (size_t)r*CC);
    #pragma unroll
    for (int q=0;q<6;q++){
        int idx = lane + 32*q;
        float4 vv = v4[idx], ll = l4[idx], o;
        if (s < 2){
            o.x = fmaf(mp, vv.x, ll.x); o.y = fmaf(mp, vv.y, ll.y);
            o.z = fmaf(mp, vv.z, ll.z); o.w = fmaf(mp, vv.w, ll.w);
        } else {
            o.x = mp*vv.x*ll.x; o.y = mp*vv.y*ll.y;
            o.z = mp*vv.z*ll.z; o.w = mp*vv.w*ll.w;
        }
        o4[idx] = o;
    }
}

// ---------------- TF32 tensor-core GEMM --------------------------------------
#define EPI_PROJ 1
#define EPI_DIST 2
#define EPI_FC1  3
#define EPI_FC2  4
#define SA 20   // smem row stride (floats): 20*g + t hits all 32 banks

template<bool BT, int EPI>
__global__ __launch_bounds__(256,2)
void gemm_t(const float* __restrict__ Ain, const float* __restrict__ Bin,
            float* __restrict__ Cout, const float* __restrict__ bias,
            int Nn, int K)
{
    __shared__ float As[128*SA];
    __shared__ float Bs[128*SA];
    const int tid = threadIdx.x, lane = tid&31, wid = tid>>5;
    const int wm = wid>>1, wn = wid&1;           // 4 x 2 warp grid
    const int g = lane>>2, tq = lane&3;
    const int m0 = blockIdx.y*128, n0 = blockIdx.x*128;

    const float* A = Ain; const float* B = Bin; float* C = Cout;
    const float* x2a = nullptr; const float* x2b = nullptr;
    if (EPI==EPI_DIST){
        int z = blockIdx.z, p = z>>3, b = z&7;
        A   = g_qk + ((size_t)(c_PU[p]*BB + b))*NTOK*CC;
        B   = g_qk + ((size_t)(c_PW[p]*BB + b))*NTOK*CC;
        C   = g_Dm + ((size_t)z)*NTOK*NTOK;
        x2a = g_x2 + (c_PU[p]*BB + b)*NTOK;
        x2b = g_x2 + (c_PW[p]*BB + b)*NTOK;
    }

    const int am0 = tid>>2, am1 = 64 + (tid>>2);
    const int ak4 = (tid&3)*4;
    const int bn  = tid & 127;
    const int bk4 = (tid>>7)*4;                   // 0 or 4
    float4 ra[2], rb[2];

    float acc[2][8][4];
    #pragma unroll
    for (int i=0;i<2;i++)
        #pragma unroll
        for (int j=0;j<8;j++)
            #pragma unroll
            for (int e=0;e<4;e++) acc[i][j][e]=0.f;

    // prologue loads
    ra[0] = *(const float4*)(A + (size_t)(m0+am0)*K + ak4);
    ra[1] = *(const float4*)(A + (size_t)(m0+am1)*K + ak4);
    if (BT){
        rb[0] = *(const float4*)(B + (size_t)(n0+am0)*K + ak4);
        rb[1] = *(const float4*)(B + (size_t)(n0+am1)*K + ak4);
    } else {
        #pragma unroll
        for (int l=0;l<2;l++){
            int kk = bk4 + l*8;
            rb[l].x = B[(size_t)(kk+0)*Nn + n0 + bn];
            rb[l].y = B[(size_t)(kk+1)*Nn + n0 + bn];
            rb[l].z = B[(size_t)(kk+2)*Nn + n0 + bn];
            rb[l].w = B[(size_t)(kk+3)*Nn + n0 + bn];
        }
    }

    for (int k0 = 0; k0 < K; k0 += 16){
        __syncthreads();
        {   // store staged tiles (converted to tf32)
            float4 t4;
            t4.x=__uint_as_float(f2tf(ra[0].x)); t4.y=__uint_as_float(f2tf(ra[0].y));
            t4.z=__uint_as_float(f2tf(ra[0].z)); t4.w=__uint_as_float(f2tf(ra[0].w));
            *(float4*)&As[am0*SA + ak4] = t4;
            t4.x=__uint_as_float(f2tf(ra[1].x)); t4.y=__uint_as_float(f2tf(ra[1].y));
            t4.z=__uint_as_float(f2tf(ra[1].z)); t4.w=__uint_as_float(f2tf(ra[1].w));
            *(float4*)&As[am1*SA + ak4] = t4;
            if (BT){
                t4.x=__uint_as_float(f2tf(rb[0].x)); t4.y=__uint_as_float(f2tf(rb[0].y));
                t4.z=__uint_as_float(f2tf(rb[0].z)); t4.w=__uint_as_float(f2tf(rb[0].w));
                *(float4*)&Bs[am0*SA + ak4] = t4;
                t4.x=__uint_as_float(f2tf(rb[1].x)); t4.y=__uint_as_float(f2tf(rb[1].y));
                t4.z=__uint_as_float(f2tf(rb[1].z)); t4.w=__uint_as_float(f2tf(rb[1].w));
                *(float4*)&Bs[am1*SA + ak4] = t4;
            } else {
                #pragma unroll
                for (int l=0;l<2;l++){
                    t4.x=__uint_as_float(f2tf(rb[l].x)); t4.y=__uint_as_float(f2tf(rb[l].y));
                    t4.z=__uint_as_float(f2tf(rb[l].z)); t4.w=__uint_as_float(f2tf(rb[l].w));
                    *(float4*)&Bs[bn*SA + bk4 + l*8] = t4;
                }
            }
        }
        __syncthreads();
        if (k0 + 16 < K){   // prefetch next tile during MMA
            int kn = k0 + 16;
            ra[0] = *(const float4*)(A + (size_t)(m0+am0)*K + kn + ak4);
            ra[1] = *(const float4*)(A + (size_t)(m0+am1)*K + kn + ak4);
            if (BT){
                rb[0] = *(const float4*)(B + (size_t)(n0+am0)*K + kn + ak4);
                rb[1] = *(const float4*)(B + (size_t)(n0+am1)*K + kn + ak4);
            } else {
                #pragma unroll
                for (int l=0;l<2;l++){
                    int kk = kn + bk4 + l*8;
                    rb[l].x = B[(size_t)(kk+0)*Nn + n0 + bn];
                    rb[l].y = B[(size_t)(kk+1)*Nn + n0 + bn];
                    rb[l].z = B[(size_t)(kk+2)*Nn + n0 + bn];
                    rb[l].w = B[(size_t)(kk+3)*Nn + n0 + bn];
                }
            }
        }
        #pragma unroll
        for (int ks=0;ks<2;ks++){
            const int kk = ks*8 + tq;
            unsigned a[2][4];
            #pragma unroll
            for (int ma=0;ma<2;ma++){
                const float* pA = &As[(wm*32 + ma*16 + g)*SA + kk];
                a[ma][0] = __float_as_uint(pA[0]);
                a[ma][1] = __float_as_uint(pA[8*SA]);
                a[ma][2] = __float_as_uint(pA[4]);
                a[ma][3] = __float_as_uint(pA[8*SA+4]);
            }
            #pragma unroll
            for (int nb=0;nb<8;nb++){
                const float* pB = &Bs[(wn*64 + nb*8 + g)*SA + kk];
                unsigned bq[2] = { __float_as_uint(pB[0]), __float_as_uint(pB[4]) };
                mma8(acc[0][nb], a[0], bq);
                mma8(acc[1][nb], a[1], bq);
            }
        }
    }

    // epilogue
    #pragma unroll
    for (int ma=0;ma<2;ma++){
        int m = m0 + wm*32 + ma*16 + g;     // second row = m+8
        #pragma unroll
        for (int nb=0;nb<8;nb++){
            int n = n0 + wn*64 + nb*8 + 2*tq;
            float c0=acc[ma][nb][0], c1=acc[ma][nb][1];
            float c2=acc[ma][nb][2], c3=acc[ma][nb][3];
            if (EPI==EPI_PROJ){
                float b0 = bias[n], b1 = bias[n+1];
                float2 lo = { c0+b0, c1+b1 };
                float2 hi = { c2+b0, c3+b1 };
                if (n < CC){
                    *(float2*)&g_qk[(size_t)m*CC + n]     = lo;
                    *(float2*)&g_qk[(size_t)(m+8)*CC + n] = hi;
                } else {
                    *(float2*)&g_v[(size_t)m*CC + (n-CC)]     = lo;
                    *(float2*)&g_v[(size_t)(m+8)*CC + (n-CC)] = hi;
                }
            } else if (EPI==EPI_DIST){
                float xa0 = x2a[m], xa1 = x2a[m+8];
                float xb0 = x2b[n], xb1 = x2b[n+1];
                float2 lo = { sqrtf(fmaxf(xa0+xb0-2.f*c0, 1e-12f)),
                              sqrtf(fmaxf(xa0+xb1-2.f*c1, 1e-12f)) };
                float2 hi = { sqrtf(fmaxf(xa1+xb0-2.f*c2, 1e-12f)),
                              sqrtf(fmaxf(xa1+xb1-2.f*c3, 1e-12f)) };
                *(float2*)&C[(size_t)m*NTOK + n]     = lo;
                *(float2*)&C[(size_t)(m+8)*NTOK + n] = hi;
            } else if (EPI==EPI_FC1){
                float b0 = bias[n], b1 = bias[n+1];
                float v0 = c0+b0, v1 = c1+b1, v2 = c2+b0, v3 = c3+b1;
                v0 = 0.5f*v0*(1.f+erff(v0*0.70710678118654752f));
                v1 = 0.5f*v1*(1.f+erff(v1*0.70710678118654752f));
                v2 = 0.5f*v2*(1.f+erff(v2*0.70710678118654752f));
                v3 = 0.5f*v3*(1.f+erff(v3*0.70710678118654752f));
                *(float2*)&C[(size_t)m*Nn + n]     = make_float2(v0, v1);
                *(float2*)&C[(size_t)(m+8)*Nn + n] = make_float2(v2, v3);
            } else { // EPI_FC2: residual add
                float b0 = bias[n], b1 = bias[n+1];
                float* p0 = &C[(size_t)m*Nn + n];
                float* p1 = &C[(size_t)(m+8)*Nn + n];
                p0[0] += c0 + b0; p0[1] += c1 + b1;
                p1[0] += c2 + b0; p1[1] += c3 + b1;
            }
        }
    }
}

// ---------------- distance-matrix reductions (all pairs, one launch each) ----
__global__ __launch_bounds__(256)
void k_rowstats(){
    int r = blockIdx.x*8 + (threadIdx.x>>5);   // 0..122879
    int lane = threadIdx.x & 31;
    int z = r>>10, p = z>>3;
    const float4* row = (const float4*)(g_Dm + ((size_t)z<<20) + ((size_t)(r&1023)<<10));
    float4 v[8];
    #pragma unroll
    for (int q=0;q<8;q++) v[q] = row[lane + 32*q];
    float c = __shfl_sync(~0u, v[0].x, 0);
    float s1=0.f, s2=0.f, mn=3.4e38f, mx=0.f;
    #pragma unroll
    for (int q=0;q<8;q++){
        float a0=v[q].x, a1=v[q].y, a2=v[q].z, a3=v[q].w;
        float d0=a0-c, d1=a1-c, d2=a2-c, d3=a3-c;
        s1 += d0+d1+d2+d3;
        s2 += d0*d0 + d1*d1 + d2*d2 + d3*d3;
        mn = fminf(mn, fminf(fminf(a0,a1), fminf(a2,a3)));
        mx = fmaxf(mx, fmaxf(fmaxf(a0,a1), fmaxf(a2,a3)));
    }
    s1 = wsum(s1); s2 = wsum(s2); mn = wmin(mn); mx = wmax(mx);
    if (lane==0){
        g_rc[r]=c; g_rs1[r]=s1; g_rs2[r]=s2;
        atomicMin(&g_minu[p], __float_as_uint(mn));
        atomicMax(&g_maxu[p], __float_as_uint(mx));
    }
}

__global__ __launch_bounds__(256)
void k_colstats(){
    int id = blockIdx.x*256 + threadIdx.x;     // 0..122879
    int z = id>>10, j = id&1023;
    const float* base = g_Dm + ((size_t)z<<20) + j;
    float c = base[0];
    float s1=0.f, s2=0.f;
    #pragma unroll 4
    for (int i=0;i<NTOK;i++){
        float d = base[(size_t)i<<10] - c;
        s1 += d; s2 += d*d;
    }
    g_cc[id]=c; g_cs1[id]=s1; g_cs2[id]=s2;
}

__global__ __launch_bounds__(256)
void k_finalize(){
    int id = blockIdx.x*256 + threadIdx.x;     // 0..245759
    int side = id / (ZTOT*NTOK);
    int r = id % (ZTOT*NTOK);
    int p = r>>13;
    float t = (p<3) ? __uint_as_float(g_maxu[p]) : __uint_as_float(g_minu[p]);
    float c, s1, s2;
    if (side==0){ c=g_rc[r]; s1=g_rs1[r]; s2=g_rs2[r]; }
    else        { c=g_cc[r]; s1=g_cs1[r]; s2=g_cs2[r]; }
    float ct = c - t;
    float ss = s2 + 2.f*ct*s1 + (float)NTOK*ct*ct;
    float inv = 1.f / fmaxf(sqrtf(fmaxf(ss, 0.f)), 1e-12f);
    if (side==0) g_invr[r]=inv; else g_invc[r]=inv;
}

__global__ __launch_bounds__(256)
void k_accum_col(const float* __restrict__ theta, const float* __restrict__ alpha){
    int id = blockIdx.x*256 + threadIdx.x;     // 0..122879
    int z = id>>10, j = id&1023, p = z>>3, b = z&7;
    float t = (p<3) ? __uint_as_float(g_maxu[p]) : __uint_as_float(g_minu[p]);
    float sc = calc_sc(c_WC[p], *theta, *alpha);
    const float* base = g_Dm + ((size_t)z<<20) + j;
    const float* ir = g_invr + (z<<10);
    float s = 0.f;
    #pragma unroll 4
    for (int i=0;i<NTOK;i++)
        s += (base[(size_t)i<<10] - t) * ir[i];
    atomicAdd(&g_map[c_PW[p]*BN + b*NTOK + j], sc*s);
}

__global__ __launch_bounds__(256)
void k_accum_row(const float* __restrict__ theta, const float* __restrict__ alpha){
    int r = blockIdx.x*8 + (threadIdx.x>>5);   // 0..122879
    int lane = threadIdx.x & 31;
    int z = r>>10, p = z>>3, b = z&7, i = r&1023;
    float t = (p<3) ? __uint_as_float(g_maxu[p]) : __uint_as_float(g_minu[p]);
    float sc = calc_sc(c_WR[p], *theta, *alpha);
    const float4* row = (const float4*)(g_Dm + ((size_t)z<<20) + ((size_t)i<<10));
    const float4* ic  = (const float4*)(g_invc + (z<<10));
    float s = 0.f;
    #pragma unroll
    for (int q=0;q<8;q++){
        float4 d = row[lane+32*q];
        float4 w = ic [lane+32*q];
        s += (d.x-t)*w.x + (d.y-t)*w.y + (d.z-t)*w.z + (d.w-t)*w.w;
    }
    s = wsum(s);
    if (lane==0) atomicAdd(&g_map[c_PU[p]*BN + b*NTOK + i], sc*s);
}

// ---------------- host orchestration ----------------------------------------
extern "C" void kernel_launch(void* const* d_in, const int* in_sizes, int n_in,
                              void* d_out, int out_size)
{
    const float* anchor   = (const float*)d_in[0];
    const float* positive = (const float*)d_in[1];
    const float* neg1     = (const float*)d_in[2];
    const float* neg2     = (const float*)d_in[3];
    const float* n1w      = (const float*)d_in[4];
    const float* n1b      = (const float*)d_in[5];
    const float* n2w      = (const float*)d_in[6];
    const float* n2b      = (const float*)d_in[7];
    const float* projW    = (const float*)d_in[8];
    const float* projB    = (const float*)d_in[9];
    const float* fc1W     = (const float*)d_in[10];
    const float* fc1B     = (const float*)d_in[11];
    const float* fc2W     = (const float*)d_in[12];
    const float* fc2B     = (const float*)d_in[13];
    const float* theta    = (const float*)d_in[14];
    const float* alpha    = (const float*)d_in[15];
    float* out = (float*)d_out;

    float *p_ln, *p_hid;
    cudaGetSymbolAddress((void**)&p_ln,  g_ln);
    cudaGetSymbolAddress((void**)&p_hid, g_hid);

    k_zero_map<<<ROWS/256, 256>>>();
    k_ln_gather<<<ROWS/8, 256>>>(anchor, positive, neg1, neg2, n1w, n1b);

    // projection: (49152 x 768) @ (768 x 1536) -> split qk | v (in-kernel)
    gemm_t<false, EPI_PROJ><<<dim3(POUT/128, ROWS/128, 1), 256>>>(
        p_ln, projW, nullptr, projB, POUT, CC);

    k_x2<<<ROWS/8, 256>>>();
    k_reset<<<1, 32>>>();

    // all 15 pairs x 8 batches in one batched dist GEMM
    gemm_t<true, EPI_DIST><<<dim3(NTOK/128, NTOK/128, ZTOT), 256>>>(
        nullptr, nullptr, nullptr, nullptr, NTOK, CC);

    k_rowstats<<<(ZTOT*NTOK)/8, 256>>>();
    k_colstats<<<(ZTOT*NTOK)/256, 256>>>();
    k_finalize<<<(2*ZTOT*NTOK)/256, 256>>>();
    k_accum_col<<<(ZTOT*NTOK)/256, 256>>>(theta, alpha);
    k_accum_row<<<(ZTOT*NTOK)/8, 256>>>(theta, alpha);

    k_stage_d<<<ROWS/8, 256>>>(out);
    k_ln_plain<<<ROWS/8, 256>>>(out, n2w, n2b);

    gemm_t<false, EPI_FC1><<<dim3(HID/128, ROWS/128, 1), 256>>>(
        p_ln, fc1W, p_hid, fc1B, HID, CC);
    gemm_t<false, EPI_FC2><<<dim3(CC/128, ROWS/128, 1), 256>>>(
        p_hid, fc2W, out, fc2B, CC, HID);
}

// round 6
// speedup vs baseline: 6.2556x; 1.2057x over previous
#include <cuda_runtime.h>
#include <math.h>
#include <stdint.h>

#define BB    8
#define NTOK  1024
#define CC    768
#define BN    (BB*NTOK)          // 8192
#define ROWS  (6*BN)             // 49152
#define HID   3072
#define POUT  1536
#define NPAIR 15
#define ZTOT  (NPAIR*BB)         // 120

// ---------------- scratch ----------------------------------------------------
__device__ float g_ln [(size_t)ROWS*CC];
__device__ float g_qk [(size_t)ROWS*CC];
__device__ float g_v  [(size_t)ROWS*CC];
__device__ float g_x2 [ROWS];
__device__ float g_Dm [(size_t)ZTOT*NTOK*NTOK];      // 503 MB
__device__ float g_rc [ZTOT*NTOK], g_rs1[ZTOT*NTOK], g_rs2[ZTOT*NTOK];
__device__ float g_cc [ZTOT*NTOK], g_cs1[ZTOT*NTOK], g_cs2[ZTOT*NTOK];
__device__ float g_invr[ZTOT*NTOK], g_invc[ZTOT*NTOK];
__device__ unsigned g_minu[NPAIR], g_maxu[NPAIR];
__device__ float g_map[ROWS];
__device__ float g_hid[(size_t)ROWS*HID];
__device__ float g_wt [(size_t)768*(1536+3072) + (size_t)3072*768]; // transposed weights

__constant__ int c_PU[NPAIR] = {1,3,5, 0,0,0,0, 1,1,1,1, 2,2,3,3};
__constant__ int c_PW[NPAIR] = {0,2,4, 2,3,4,5, 2,3,4,5, 4,5,4,5};
__constant__ int c_WC[NPAIR] = {0,0,0, 1,1,1,1, 1,1,1,1, 2,2,2,2};
__constant__ int c_WR[NPAIR] = {0,0,0, 1,1,2,2, 1,1,2,2, 2,2,2,2};

// ---------------- helpers ----------------------------------------------------
__device__ __forceinline__ float wsum(float v){
    #pragma unroll
    for (int o=16;o;o>>=1) v += __shfl_xor_sync(~0u, v, o);
    return v;
}
__device__ __forceinline__ float wmin(float v){
    #pragma unroll
    for (int o=16;o;o>>=1) v = fminf(v, __shfl_xor_sync(~0u, v, o));
    return v;
}
__device__ __forceinline__ float wmax(float v){
    #pragma unroll
    for (int o=16;o;o>>=1) v = fmaxf(v, __shfl_xor_sync(~0u, v, o));
    return v;
}
__device__ __forceinline__ float f2tf(float x){
    unsigned r; asm("cvt.rna.tf32.f32 %0, %1;" : "=r"(r) : "f"(x));
    return __uint_as_float(r);
}
__device__ __forceinline__ void mma8(float* c, const unsigned* a, const unsigned* b){
    asm volatile("mma.sync.aligned.m16n8k8.row.col.f32.tf32.tf32.f32 "
        "{%0,%1,%2,%3}, {%4,%5,%6,%7}, {%8,%9}, {%0,%1,%2,%3};"
        : "+f"(c[0]),"+f"(c[1]),"+f"(c[2]),"+f"(c[3])
        : "r"(a[0]),"r"(a[1]),"r"(a[2]),"r"(a[3]), "r"(b[0]),"r"(b[1]));
}
__device__ __forceinline__ float calc_sc(int wsel, float th, float al){
    if (wsel==0) return -1.f;
    float kk = tanhf(th) + 1.f;
    float a  = 1.f/(1.f + expf(-al));
    return 0.5f*kk*((wsel==1)? a : (1.f-a));
}
__device__ __forceinline__ uint32_t smem_u32(const void* p){
    uint32_t a;
    asm("{ .reg .u64 t; cvta.to.shared.u64 t, %1; cvt.u32.u64 %0, t; }" : "=r"(a) : "l"(p));
    return a;
}
#define CP16(dst, src) asm volatile("cp.async.cg.shared.global [%0], [%1], 16;" :: "r"(dst), "l"(src))
#define CP_COMMIT()    asm volatile("cp.async.commit_group;" ::: "memory")
#define CP_WAIT1()     asm volatile("cp.async.wait_group 1;" ::: "memory")

// ---------------- layernorm / elementwise ------------------------------------
__global__ __launch_bounds__(256)
void k_ln_gather(const float* __restrict__ anc, const float* __restrict__ pos,
                 const float* __restrict__ n1,  const float* __restrict__ n2,
                 const float* __restrict__ w,   const float* __restrict__ b)
{
    int r = blockIdx.x*8 + (threadIdx.x>>5);
    int lane = threadIdx.x & 31;
    int s = r / BN, i = r % BN;
    const float* src;
    if (s==0)       src = anc + (size_t)i*CC;
    else if (s==1)  src = pos + (size_t)i*CC;
    else if (s<4)   src = n1 + ((size_t)(s-2)*BN + i)*CC;
    else            src = n2 + ((size_t)(s-4)*BN + i)*CC;
    const float4* p4 = (const float4*)src;
    float4 v[6]; float ls = 0.f;
    #pragma unroll
    for (int q=0;q<6;q++){ v[q] = p4[lane+32*q]; ls += v[q].x+v[q].y+v[q].z+v[q].w; }
    float mu = wsum(ls) * (1.f/CC);
    float lv = 0.f;
    #pragma unroll
    for (int q=0;q<6;q++){
        float a0=v[q].x-mu, a1=v[q].y-mu, a2=v[q].z-mu, a3=v[q].w-mu;
        lv += a0*a0 + a1*a1 + a2*a2 + a3*a3;
    }
    float inv = rsqrtf(wsum(lv)*(1.f/CC) + 1e-5f);
    float4* dst = (float4*)(g_ln + (size_t)r*CC);
    const float4* w4 = (const float4*)w; const float4* b4 = (const float4*)b;
    #pragma unroll
    for (int q=0;q<6;q++){
        int idx = lane + 32*q;
        float4 ww = w4[idx], bb = b4[idx], o;
        o.x = (v[q].x-mu)*inv*ww.x + bb.x;
        o.y = (v[q].y-mu)*inv*ww.y + bb.y;
        o.z = (v[q].z-mu)*inv*ww.z + bb.z;
        o.w = (v[q].w-mu)*inv*ww.w + bb.w;
        dst[idx] = o;
    }
}

__global__ __launch_bounds__(256)
void k_ln_plain(const float* __restrict__ in, const float* __restrict__ w,
                const float* __restrict__ b)
{
    int r = blockIdx.x*8 + (threadIdx.x>>5);
    int lane = threadIdx.x & 31;
    const float4* p4 = (const float4*)(in + (size_t)r*CC);
    float4 v[6]; float ls = 0.f;
    #pragma unroll
    for (int q=0;q<6;q++){ v[q] = p4[lane+32*q]; ls += v[q].x+v[q].y+v[q].z+v[q].w; }
    float mu = wsum(ls) * (1.f/CC);
    float lv = 0.f;
    #pragma unroll
    for (int q=0;q<6;q++){
        float a0=v[q].x-mu, a1=v[q].y-mu, a2=v[q].z-mu, a3=v[q].w-mu;
        lv += a0*a0 + a1*a1 + a2*a2 + a3*a3;
    }
    float inv = rsqrtf(wsum(lv)*(1.f/CC) + 1e-5f);
    float4* dst = (float4*)(g_ln + (size_t)r*CC);
    const float4* w4 = (const float4*)w; const float4* b4 = (const float4*)b;
    #pragma unroll
    for (int q=0;q<6;q++){
        int idx = lane + 32*q;
        float4 ww = w4[idx], bb = b4[idx], o;
        o.x = (v[q].x-mu)*inv*ww.x + bb.x;
        o.y = (v[q].y-mu)*inv*ww.y + bb.y;
        o.z = (v[q].z-mu)*inv*ww.z + bb.z;
        o.w = (v[q].w-mu)*inv*ww.w + bb.w;
        dst[idx] = o;
    }
}

__global__ __launch_bounds__(256)
void k_x2(){
    int r = blockIdx.x*8 + (threadIdx.x>>5);
    int lane = threadIdx.x & 31;
    const float4* p4 = (const float4*)(g_qk + (size_t)r*CC);
    float s = 0.f;
    #pragma unroll
    for (int q=0;q<6;q++){
        float4 v = p4[lane+32*q];
        s += v.x*v.x + v.y*v.y + v.z*v.z + v.w*v.w;
    }
    s = wsum(s);
    if (lane==0) g_x2[r] = s;
}

__global__ __launch_bounds__(256)
void k_zero_map(){
    int i = blockIdx.x*256 + threadIdx.x;
    if (i < ROWS) g_map[i] = 0.f;
}

__global__ void k_reset(){
    int i = threadIdx.x;
    if (i < NPAIR){ g_minu[i] = 0x7f7fffffu; g_maxu[i] = 0u; }
}

__global__ __launch_bounds__(256)
void k_stage_d(float* __restrict__ out){
    int r = blockIdx.x*8 + (threadIdx.x>>5);
    int lane = threadIdx.x & 31;
    int s = r / BN;
    float mp = g_map[r];
    const float4* v4 = (const float4*)(g_v  + (size_t)r*CC);
    const float4* l4 = (const float4*)(g_ln + (size_t)r*CC);
    float4* o4 = (float4*)(out + (size_t)r*CC);
    #pragma unroll
    for (int q=0;q<6;q++){
        int idx = lane + 32*q;
        float4 vv = v4[idx], ll = l4[idx], o;
        if (s < 2){
            o.x = fmaf(mp, vv.x, ll.x); o.y = fmaf(mp, vv.y, ll.y);
            o.z = fmaf(mp, vv.z, ll.z); o.w = fmaf(mp, vv.w, ll.w);
        } else {
            o.x = mp*vv.x*ll.x; o.y = mp*vv.y*ll.y;
            o.z = mp*vv.z*ll.z; o.w = mp*vv.w*ll.w;
        }
        o4[idx] = o;
    }
}

// weight transpose: W[K][N] -> WT[N][K], rounded to tf32
__global__ __launch_bounds__(256)
void k_transpose(const float* __restrict__ W, float* __restrict__ WT, int K, int N){
    __shared__ float t[32][33];
    int k0 = blockIdx.x*32, n0 = blockIdx.y*32;
    int tx = threadIdx.x & 31, ty = threadIdx.x >> 5;   // 32 x 8
    #pragma unroll
    for (int i=0;i<32;i+=8)
        t[ty+i][tx] = f2tf(W[(size_t)(k0+ty+i)*N + n0+tx]);
    __syncthreads();
    #pragma unroll
    for (int i=0;i<32;i+=8)
        WT[(size_t)(n0+ty+i)*K + k0+tx] = t[tx][ty+i];
}

// ---------------- pipelined tf32 mma.sync GEMM (NT only) ---------------------
// C[M x Nn] = A[M x K](K-major) @ B[Nn x K](K-major)^T
// tiles 128x128, BK=32, 3-stage cp.async pipeline, 8 warps (4m x 2n), warp 32x64
#define EPI_PROJ 1
#define EPI_DIST 2
#define EPI_FC1  3
#define EPI_FC2  4

#define SROW 36                        // smem row stride in floats
#define STG_F (2*128*SROW)             // floats per stage (A+B) = 9216
#define SMEM_BYTES (3*STG_F*4)         // 110592

template<int EPI>
__device__ __forceinline__ void ld_stage(uint32_t sb, int stage,
        const float* A, const float* B, int K, int k0, int m0, int n0, int tid)
{
    int r0 = tid>>3, q = tid&7;
    uint32_t sA = sb + (uint32_t)stage*(STG_F*4);
    uint32_t sB = sA + 128*SROW*4;
    #pragma unroll
    for (int l=0;l<4;l++){
        int row = r0 + 32*l;
        CP16(sA + row*(SROW*4) + q*16, A + (size_t)(m0+row)*K + k0 + q*4);
        CP16(sB + row*(SROW*4) + q*16, B + (size_t)(n0+row)*K + k0 + q*4);
    }
}

template<int EPI>
__global__ __launch_bounds__(256,2)
void gemm_t2(const float* __restrict__ Ain, const float* __restrict__ Bin,
             float* __restrict__ Cout, const float* __restrict__ bias,
             int Nn, int K)
{
    extern __shared__ float smem[];
    uint32_t sb = smem_u32(smem);
    const int tid = threadIdx.x, lane = tid&31, wid = tid>>5;
    const int wm = wid>>1, wn = wid&1;          // 4 x 2 warps
    const int g = lane>>2, tq = lane&3;
    const int m0 = blockIdx.y*128, n0 = blockIdx.x*128;

    const float* A = Ain; const float* B = Bin; float* C = Cout;
    const float* x2a = nullptr; const float* x2b = nullptr;
    if (EPI==EPI_DIST){
        int z = blockIdx.z, p = z>>3, bq = z&7;
        A   = g_qk + ((size_t)(c_PU[p]*BB + bq))*NTOK*CC;
        B   = g_qk + ((size_t)(c_PW[p]*BB + bq))*NTOK*CC;
        C   = g_Dm + ((size_t)z)*NTOK*NTOK;
        x2a = g_x2 + (c_PU[p]*BB + bq)*NTOK;
        x2b = g_x2 + (c_PW[p]*BB + bq)*NTOK;
    }

    float acc[2][8][4];
    #pragma unroll
    for (int i=0;i<2;i++)
        #pragma unroll
        for (int j=0;j<8;j++)
            #pragma unroll
            for (int e=0;e<4;e++) acc[i][j][e]=0.f;

    const int nkc = K >> 5;
    // preload stages 0,1
    ld_stage<EPI>(sb, 0, A, B, K, 0,  m0, n0, tid); CP_COMMIT();
    ld_stage<EPI>(sb, 1, A, B, K, 32, m0, n0, tid); CP_COMMIT();

    for (int kc=0; kc<nkc; kc++){
        CP_WAIT1();
        __syncthreads();
        // issue loads for chunk kc+2 into the slot freed by chunk kc-1
        if (kc+2 < nkc)
            ld_stage<EPI>(sb, (kc+2)%3, A, B, K, (kc+2)<<5, m0, n0, tid);
        CP_COMMIT();   // unconditional: keeps wait_group(1) semantics at the tail

        const float* As = smem + (kc%3)*STG_F;
        const float* Bs = As + 128*SROW;
        #pragma unroll
        for (int ks=0;ks<4;ks++){
            const int kk = ks*8 + tq;
            unsigned a[2][4];
            #pragma unroll
            for (int ma=0;ma<2;ma++){
                const float* pA = &As[(wm*32 + ma*16 + g)*SROW + kk];
                a[ma][0] = __float_as_uint(pA[0]);
                a[ma][1] = __float_as_uint(pA[8*SROW]);
                a[ma][2] = __float_as_uint(pA[4]);
                a[ma][3] = __float_as_uint(pA[8*SROW+4]);
            }
            #pragma unroll
            for (int nb=0;nb<8;nb++){
                const float* pB = &Bs[(wn*64 + nb*8 + g)*SROW + kk];
                unsigned bq2[2] = { __float_as_uint(pB[0]), __float_as_uint(pB[4]) };
                mma8(acc[0][nb], a[0], bq2);
                mma8(acc[1][nb], a[1], bq2);
            }
        }
    }

    // epilogue
    #pragma unroll
    for (int ma=0;ma<2;ma++){
        int m = m0 + wm*32 + ma*16 + g;     // second row = m+8
        #pragma unroll
        for (int nb=0;nb<8;nb++){
            int n = n0 + wn*64 + nb*8 + 2*tq;
            float c0=acc[ma][nb][0], c1=acc[ma][nb][1];
            float c2=acc[ma][nb][2], c3=acc[ma][nb][3];
            if (EPI==EPI_PROJ){
                float b0 = bias[n], b1 = bias[n+1];
                if (n < CC){
                    // qk: round to tf32 so dist GEMM operands are exact tf32
                    float2 lo = { f2tf(c0+b0), f2tf(c1+b1) };
                    float2 hi = { f2tf(c2+b0), f2tf(c3+b1) };
                    *(float2*)&g_qk[(size_t)m*CC + n]     = lo;
                    *(float2*)&g_qk[(size_t)(m+8)*CC + n] = hi;
                } else {
                    float2 lo = { c0+b0, c1+b1 };
                    float2 hi = { c2+b0, c3+b1 };
                    *(float2*)&g_v[(size_t)m*CC + (n-CC)]     = lo;
                    *(float2*)&g_v[(size_t)(m+8)*CC + (n-CC)] = hi;
                }
            } else if (EPI==EPI_DIST){
                float xa0 = x2a[m], xa1 = x2a[m+8];
                float xb0 = x2b[n], xb1 = x2b[n+1];
                float2 lo = { sqrtf(fmaxf(xa0+xb0-2.f*c0, 1e-12f)),
                              sqrtf(fmaxf(xa0+xb1-2.f*c1, 1e-12f)) };
                float2 hi = { sqrtf(fmaxf(xa1+xb0-2.f*c2, 1e-12f)),
                              sqrtf(fmaxf(xa1+xb1-2.f*c3, 1e-12f)) };
                *(float2*)&C[(size_t)m*NTOK + n]     = lo;
                *(float2*)&C[(size_t)(m+8)*NTOK + n] = hi;
            } else if (EPI==EPI_FC1){
                float b0 = bias[n], b1 = bias[n+1];
                float v0 = c0+b0, v1 = c1+b1, v2 = c2+b0, v3 = c3+b1;
                v0 = 0.5f*v0*(1.f+erff(v0*0.70710678118654752f));
                v1 = 0.5f*v1*(1.f+erff(v1*0.70710678118654752f));
                v2 = 0.5f*v2*(1.f+erff(v2*0.70710678118654752f));
                v3 = 0.5f*v3*(1.f+erff(v3*0.70710678118654752f));
                // round: fc2 consumes g_hid as exact tf32
                *(float2*)&C[(size_t)m*Nn + n]     = make_float2(f2tf(v0), f2tf(v1));
                *(float2*)&C[(size_t)(m+8)*Nn + n] = make_float2(f2tf(v2), f2tf(v3));
            } else { // EPI_FC2: residual add
                float b0 = bias[n], b1 = bias[n+1];
                float* p0 = &C[(size_t)m*Nn + n];
                float* p1 = &C[(size_t)(m+8)*Nn + n];
                p0[0] += c0 + b0; p0[1] += c1 + b1;
                p1[0] += c2 + b0; p1[1] += c3 + b1;
            }
        }
    }
}

// ---------------- distance-matrix reductions ---------------------------------
__global__ __launch_bounds__(256)
void k_rowstats(){
    int r = blockIdx.x*8 + (threadIdx.x>>5);
    int lane = threadIdx.x & 31;
    int z = r>>10, p = z>>3;
    const float4* row = (const float4*)(g_Dm + ((size_t)z<<20) + ((size_t)(r&1023)<<10));
    float4 v[8];
    #pragma unroll
    for (int q=0;q<8;q++) v[q] = row[lane + 32*q];
    float c = __shfl_sync(~0u, v[0].x, 0);
    float s1=0.f, s2=0.f, mn=3.4e38f, mx=0.f;
    #pragma unroll
    for (int q=0;q<8;q++){
        float a0=v[q].x, a1=v[q].y, a2=v[q].z, a3=v[q].w;
        float d0=a0-c, d1=a1-c, d2=a2-c, d3=a3-c;
        s1 += d0+d1+d2+d3;
        s2 += d0*d0 + d1*d1 + d2*d2 + d3*d3;
        mn = fminf(mn, fminf(fminf(a0,a1), fminf(a2,a3)));
        mx = fmaxf(mx, fmaxf(fmaxf(a0,a1), fmaxf(a2,a3)));
    }
    s1 = wsum(s1); s2 = wsum(s2); mn = wmin(mn); mx = wmax(mx);
    if (lane==0){
        g_rc[r]=c; g_rs1[r]=s1; g_rs2[r]=s2;
        atomicMin(&g_minu[p], __float_as_uint(mn));
        atomicMax(&g_maxu[p], __float_as_uint(mx));
    }
}

__global__ __launch_bounds__(256)
void k_colstats(){
    int id = blockIdx.x*256 + threadIdx.x;
    int z = id>>10;
    const float* base = g_Dm + ((size_t)z<<20) + (id&1023);
    float c = base[0];
    float s1=0.f, s2=0.f;
    #pragma unroll 4
    for (int i=0;i<NTOK;i++){
        float d = base[(size_t)i<<10] - c;
        s1 += d; s2 += d*d;
    }
    g_cc[id]=c; g_cs1[id]=s1; g_cs2[id]=s2;
}

__global__ __launch_bounds__(256)
void k_finalize(){
    int id = blockIdx.x*256 + threadIdx.x;
    int side = id / (ZTOT*NTOK);
    int r = id % (ZTOT*NTOK);
    int p = r>>13;
    float t = (p<3) ? __uint_as_float(g_maxu[p]) : __uint_as_float(g_minu[p]);
    float c, s1, s2;
    if (side==0){ c=g_rc[r]; s1=g_rs1[r]; s2=g_rs2[r]; }
    else        { c=g_cc[r]; s1=g_cs1[r]; s2=g_cs2[r]; }
    float ct = c - t;
    float ss = s2 + 2.f*ct*s1 + (float)NTOK*ct*ct;
    float inv = 1.f / fmaxf(sqrtf(fmaxf(ss, 0.f)), 1e-12f);
    if (side==0) g_invr[r]=inv; else g_invc[r]=inv;
}

__global__ __launch_bounds__(256)
void k_accum_col(const float* __restrict__ theta, const float* __restrict__ alpha){
    int id = blockIdx.x*256 + threadIdx.x;
    int z = id>>10, j = id&1023, p = z>>3, b = z&7;
    float t = (p<3) ? __uint_as_float(g_maxu[p]) : __uint_as_float(g_minu[p]);
    float sc = calc_sc(c_WC[p], *theta, *alpha);
    const float* base = g_Dm + ((size_t)z<<20) + j;
    const float* ir = g_invr + (z<<10);
    float s = 0.f;
    #pragma unroll 4
    for (int i=0;i<NTOK;i++)
        s += (base[(size_t)i<<10] - t) * ir[i];
    atomicAdd(&g_map[c_PW[p]*BN + b*NTOK + j], sc*s);
}

__global__ __launch_bounds__(256)
void k_accum_row(const float* __restrict__ theta, const float* __restrict__ alpha){
    int r = blockIdx.x*8 + (threadIdx.x>>5);
    int lane = threadIdx.x & 31;
    int z = r>>10, p = z>>3, b = z&7, i = r&1023;
    float t = (p<3) ? __uint_as_float(g_maxu[p]) : __uint_as_float(g_minu[p]);
    float sc = calc_sc(c_WR[p], *theta, *alpha);
    const float4* row = (const float4*)(g_Dm + ((size_t)z<<20) + ((size_t)i<<10));
    const float4* ic  = (const float4*)(g_invc + (z<<10));
    float s = 0.f;
    #pragma unroll
    for (int q=0;q<8;q++){
        float4 d = row[lane+32*q];
        float4 w = ic [lane+32*q];
        s += (d.x-t)*w.x + (d.y-t)*w.y + (d.z-t)*w.z + (d.w-t)*w.w;
    }
    s = wsum(s);
    if (lane==0) atomicAdd(&g_map[c_PU[p]*BN + b*NTOK + i], sc*s);
}

// ---------------- host orchestration ----------------------------------------
extern "C" void kernel_launch(void* const* d_in, const int* in_sizes, int n_in,
                              void* d_out, int out_size)
{
    const float* anchor   = (const float*)d_in[0];
    const float* positive = (const float*)d_in[1];
    const float* neg1     = (const float*)d_in[2];
    const float* neg2     = (const float*)d_in[3];
    const float* n1w      = (const float*)d_in[4];
    const float* n1b      = (const float*)d_in[5];
    const float* n2w      = (const float*)d_in[6];
    const float* n2b      = (const float*)d_in[7];
    const float* projW    = (const float*)d_in[8];
    const float* projB    = (const float*)d_in[9];
    const float* fc1W     = (const float*)d_in[10];
    const float* fc1B     = (const float*)d_in[11];
    const float* fc2W     = (const float*)d_in[12];
    const float* fc2B     = (const float*)d_in[13];
    const float* theta    = (const float*)d_in[14];
    const float* alpha    = (const float*)d_in[15];
    float* out = (float*)d_out;

    float *p_ln, *p_hid, *p_wt;
    cudaGetSymbolAddress((void**)&p_ln,  g_ln);
    cudaGetSymbolAddress((void**)&p_hid, g_hid);
    cudaGetSymbolAddress((void**)&p_wt,  g_wt);
    float* wt_proj = p_wt;                                   // [1536 x 768]
    float* wt_fc1  = p_wt + (size_t)1536*768;                // [3072 x 768]
    float* wt_fc2  = wt_fc1 + (size_t)3072*768;              // [768 x 3072]

    cudaFuncSetAttribute(gemm_t2<EPI_PROJ>, cudaFuncAttributeMaxDynamicSharedMemorySize, SMEM_BYTES);
    cudaFuncSetAttribute(gemm_t2<EPI_DIST>, cudaFuncAttributeMaxDynamicSharedMemorySize, SMEM_BYTES);
    cudaFuncSetAttribute(gemm_t2<EPI_FC1>,  cudaFuncAttributeMaxDynamicSharedMemorySize, SMEM_BYTES);
    cudaFuncSetAttribute(gemm_t2<EPI_FC2>,  cudaFuncAttributeMaxDynamicSharedMemorySize, SMEM_BYTES);

    k_zero_map<<<ROWS/256, 256>>>();
    k_ln_gather<<<ROWS/8, 256>>>(anchor, positive, neg1, neg2, n1w, n1b);
    k_transpose<<<dim3(CC/32,  POUT/32), 256>>>(projW, wt_proj, CC,  POUT);
    k_transpose<<<dim3(CC/32,  HID/32),  256>>>(fc1W,  wt_fc1,  CC,  HID);
    k_transpose<<<dim3(HID/32, CC/32),   256>>>(fc2W,  wt_fc2,  HID, CC);

    gemm_t2<EPI_PROJ><<<dim3(POUT/128, ROWS/128, 1), 256, SMEM_BYTES>>>(
        p_ln, wt_proj, nullptr, projB, POUT, CC);

    k_x2<<<ROWS/8, 256>>>();
    k_reset<<<1, 32>>>();

    gemm_t2<EPI_DIST><<<dim3(NTOK/128, NTOK/128, ZTOT), 256, SMEM_BYTES>>>(
        nullptr, nullptr, nullptr, nullptr, NTOK, CC);

    k_rowstats<<<(ZTOT*NTOK)/8, 256>>>();
    k_colstats<<<(ZTOT*NTOK)/256, 256>>>();
    k_finalize<<<(2*ZTOT*NTOK)/256, 256>>>();
    k_accum_col<<<(ZTOT*NTOK)/256, 256>>>(theta, alpha);
    k_accum_row<<<(ZTOT*NTOK)/8, 256>>>(theta, alpha);

    k_stage_d<<<ROWS/8, 256>>>(out);
    k_ln_plain<<<ROWS/8, 256>>>(out, n2w, n2b);

    gemm_t2<EPI_FC1><<<dim3(HID/128, ROWS/128, 1), 256, SMEM_BYTES>>>(
        p_ln, wt_fc1, p_hid, fc1B, HID, CC);
    gemm_t2<EPI_FC2><<<dim3(CC/128, ROWS/128, 1), 256, SMEM_BYTES>>>(
        p_hid, wt_fc2, out, fc2B, CC, HID);
}